// round 2
// baseline (speedup 1.0000x reference)
#include <cuda_runtime.h>
#include <cstdint>
#include <math.h>

#define CC 256          // channels
#define GG_MAX 4096     // graphs
#define N_MAX 500000    // nodes

__device__ float g_aw[N_MAX];
__device__ float g_comb[GG_MAX * 3 * CC];
__device__ float g_hidden[GG_MAX * CC];
__device__ int   g_is64;

// ---------------------------------------------------------------------------
// batch dtype detection: if int32 view of the buffer is sorted, data is int32.
// int64 data viewed as int32 is v0,0,v1,0,... -> unsorted once any v>0.
// (all-zero buffer: both interpretations give identical pooling)
// ---------------------------------------------------------------------------
__global__ void k0_init() { g_is64 = 0; }

__global__ void k0_detect(const int* __restrict__ b32, int N) {
    int i = blockIdx.x * blockDim.x + threadIdx.x;
    if (i < N - 1) {
        int a = b32[i], b = b32[i + 1];
        if (a > b || a < 0 || b < 0) g_is64 = 1;
    }
}

__device__ __forceinline__ long long bval(const void* b, int i) {
    if (g_is64) return ((const long long*)b)[i];
    return (long long)((const int*)b)[i];
}

// ---------------------------------------------------------------------------
// tf32 helpers
// ---------------------------------------------------------------------------
__device__ __forceinline__ uint32_t f2tf32(float f) {
    uint32_t r;
    asm("cvt.rna.tf32.f32 %0, %1;" : "=r"(r) : "f"(f));
    return r;
}

__device__ __forceinline__ void mma_tf32(float* c,
                                         uint32_t a0, uint32_t a1, uint32_t a2, uint32_t a3,
                                         uint32_t b0, uint32_t b1) {
    asm volatile(
        "mma.sync.aligned.m16n8k8.row.col.f32.tf32.tf32.f32 "
        "{%0,%1,%2,%3}, {%4,%5,%6,%7}, {%8,%9}, {%0,%1,%2,%3};\n"
        : "+f"(c[0]), "+f"(c[1]), "+f"(c[2]), "+f"(c[3])
        : "r"(a0), "r"(a1), "r"(a2), "r"(a3), "r"(b0), "r"(b1));
}

// ---------------------------------------------------------------------------
// K1: fused attention MLP -> aw[n] = sigmoid(relu(x@W1a + b1a)@W2a + b2a)
// 128 nodes per CTA, 8 warps, each warp owns a 16-row slab.
// ---------------------------------------------------------------------------
#define SA_STR 260
#define SW_STR 72
#define K1_SMEM ((128 * SA_STR + 256 * SW_STR + 512) * 4)

__global__ void __launch_bounds__(256, 1) k1_attn(
    const float* __restrict__ x, const float* __restrict__ W1a,
    const float* __restrict__ b1a, const float* __restrict__ W2a,
    const float* __restrict__ b2a, int N)
{
    extern __shared__ float sm[];
    float* sA  = sm;
    float* sW  = sm + 128 * SA_STR;
    float* sB1 = sW + 256 * SW_STR;
    float* sW2 = sB1 + 256;
    uint32_t* sAu = (uint32_t*)sA;
    uint32_t* sWu = (uint32_t*)sW;

    const int tid  = threadIdx.x;
    const int lane = tid & 31;
    const int warp = tid >> 5;
    const int m0   = blockIdx.x * 128;

    sB1[tid] = b1a[tid];
    sW2[tid] = W2a[tid];

    // Load A tile: 128 rows x 256 cols fp32 -> tf32 in smem
    #pragma unroll 4
    for (int i = 0; i < 32; ++i) {
        int idx = tid + i * 256;            // over [128 rows][64 float4]
        int row = idx >> 6;
        int c4  = idx & 63;
        int node = m0 + row;
        float4 v = make_float4(0.f, 0.f, 0.f, 0.f);
        if (node < N) v = ((const float4*)(x + (size_t)node * CC))[c4];
        uint32_t* dst = sAu + row * SA_STR + c4 * 4;
        dst[0] = f2tf32(v.x); dst[1] = f2tf32(v.y);
        dst[2] = f2tf32(v.z); dst[3] = f2tf32(v.w);
    }

    const int qr = lane >> 2;   // 0..7
    const int qc = lane & 3;    // 0..3
    const int row_lo = warp * 16 + qr;

    float p_lo = 0.f, p_hi = 0.f;

    for (int slab = 0; slab < 4; ++slab) {
        __syncthreads();  // consumers of previous W slab done (covers A tile on slab 0)
        // Load W1a column slab [256][64] -> tf32 in smem
        #pragma unroll 4
        for (int i = 0; i < 16; ++i) {
            int idx = tid + i * 256;        // over [256 k][16 float4]
            int k  = idx >> 4;
            int j4 = idx & 15;
            float4 v = ((const float4*)(W1a + (size_t)k * CC + slab * 64))[j4];
            uint32_t* dst = sWu + k * SW_STR + j4 * 4;
            dst[0] = f2tf32(v.x); dst[1] = f2tf32(v.y);
            dst[2] = f2tf32(v.z); dst[3] = f2tf32(v.w);
        }
        __syncthreads();

        float acc[8][4];
        #pragma unroll
        for (int nc = 0; nc < 8; ++nc) {
            acc[nc][0] = 0.f; acc[nc][1] = 0.f; acc[nc][2] = 0.f; acc[nc][3] = 0.f;
        }

        #pragma unroll 2
        for (int kc = 0; kc < 32; ++kc) {
            int k0 = kc * 8;
            uint32_t a0 = sAu[(row_lo)     * SA_STR + k0 + qc];
            uint32_t a1 = sAu[(row_lo + 8) * SA_STR + k0 + qc];
            uint32_t a2 = sAu[(row_lo)     * SA_STR + k0 + qc + 4];
            uint32_t a3 = sAu[(row_lo + 8) * SA_STR + k0 + qc + 4];
            #pragma unroll
            for (int nc = 0; nc < 8; ++nc) {
                uint32_t b0 = sWu[(k0 + qc)     * SW_STR + nc * 8 + qr];
                uint32_t b1 = sWu[(k0 + qc + 4) * SW_STR + nc * 8 + qr];
                mma_tf32(acc[nc], a0, a1, a2, a3, b0, b1);
            }
        }

        // epilogue: h -> relu -> * W2a, accumulate per-row scalar
        #pragma unroll
        for (int nc = 0; nc < 8; ++nc) {
            int col0 = slab * 64 + nc * 8 + qc * 2;
            float bA = sB1[col0], bB = sB1[col0 + 1];
            float wA = sW2[col0], wB = sW2[col0 + 1];
            p_lo += fmaxf(acc[nc][0] + bA, 0.f) * wA + fmaxf(acc[nc][1] + bB, 0.f) * wB;
            p_hi += fmaxf(acc[nc][2] + bA, 0.f) * wA + fmaxf(acc[nc][3] + bB, 0.f) * wB;
        }
    }

    // reduce partial dot over the 4 lanes sharing each row
    p_lo += __shfl_xor_sync(0xffffffffu, p_lo, 1);
    p_lo += __shfl_xor_sync(0xffffffffu, p_lo, 2);
    p_hi += __shfl_xor_sync(0xffffffffu, p_hi, 1);
    p_hi += __shfl_xor_sync(0xffffffffu, p_hi, 2);

    if (qc == 0) {
        float bb = b2a[0];
        int n_lo = m0 + row_lo;
        int n_hi = n_lo + 8;
        if (n_lo < N) g_aw[n_lo] = 1.f / (1.f + expf(-(p_lo + bb)));
        if (n_hi < N) g_aw[n_hi] = 1.f / (1.f + expf(-(p_hi + bb)));
    }
}

// ---------------------------------------------------------------------------
// K2: per-graph segment pooling (batch is sorted -> contiguous segments).
// One CTA per graph; thread c owns channel c. No atomics, deterministic.
// ---------------------------------------------------------------------------
__global__ void __launch_bounds__(256) k2_pool(
    const float* __restrict__ x, const void* __restrict__ batch, int N)
{
    const int g = blockIdx.x;
    __shared__ int sR[2];
    if (threadIdx.x == 0) {
        int lo = 0, hi = N;
        while (lo < hi) { int mid = (lo + hi) >> 1; if (bval(batch, mid) < (long long)g) lo = mid + 1; else hi = mid; }
        sR[0] = lo;
        hi = N;
        while (lo < hi) { int mid = (lo + hi) >> 1; if (bval(batch, mid) < (long long)g + 1) lo = mid + 1; else hi = mid; }
        sR[1] = lo;
    }
    __syncthreads();
    const int s = sR[0], e = sR[1];
    const int c = threadIdx.x;

    float sum = 0.f, att = 0.f, mx = -INFINITY;
    for (int i = s; i < e; ++i) {
        float v = x[(size_t)i * CC + c];
        float w = g_aw[i];
        sum += v;
        att = fmaf(v, w, att);
        mx = fmaxf(mx, v);
    }
    float cnt  = (float)(e - s);
    float mean = sum / fmaxf(cnt, 1.f);
    float mxo  = (e > s) ? mx : 0.f;   // empty segments -> 0 (matches isfinite mask)

    float* comb = g_comb + (size_t)g * (3 * CC);
    comb[c]          = att;
    comb[CC + c]     = mean;
    comb[2 * CC + c] = mxo;
}

// ---------------------------------------------------------------------------
// K3: fp32 tiled GEMM with bias (+optional relu). 64x64 tile, 256 threads.
// ---------------------------------------------------------------------------
template <bool RELU>
__global__ void __launch_bounds__(256) k3_gemm(
    const float* __restrict__ A, const float* __restrict__ B,
    const float* __restrict__ bias, float* __restrict__ Out,
    int M, int K, int Nn)
{
    __shared__ float sA[16][68];
    __shared__ float sB[16][68];
    const int t  = threadIdx.x;
    const int tx = t & 15, ty = t >> 4;
    const int m0 = blockIdx.y * 64, n0 = blockIdx.x * 64;
    float acc[4][4] = {};

    for (int kt = 0; kt < K; kt += 16) {
        #pragma unroll
        for (int i = 0; i < 4; ++i) {
            int idx = t + i * 256;          // [64 m][16 k]
            int m = idx >> 4, k = idx & 15;
            sA[k][m] = A[(size_t)(m0 + m) * K + kt + k];
        }
        #pragma unroll
        for (int i = 0; i < 4; ++i) {
            int idx = t + i * 256;          // [16 k][64 n]
            int k = idx >> 6, n = idx & 63;
            sB[k][n] = B[(size_t)(kt + k) * Nn + n0 + n];
        }
        __syncthreads();
        #pragma unroll
        for (int kk = 0; kk < 16; ++kk) {
            float4 a4 = *(const float4*)&sA[kk][ty * 4];
            float4 b4 = *(const float4*)&sB[kk][tx * 4];
            float av[4] = {a4.x, a4.y, a4.z, a4.w};
            float bv[4] = {b4.x, b4.y, b4.z, b4.w};
            #pragma unroll
            for (int i = 0; i < 4; ++i)
                #pragma unroll
                for (int j = 0; j < 4; ++j)
                    acc[i][j] = fmaf(av[i], bv[j], acc[i][j]);
        }
        __syncthreads();
    }

    #pragma unroll
    for (int i = 0; i < 4; ++i) {
        int m = m0 + ty * 4 + i;
        #pragma unroll
        for (int j = 0; j < 4; ++j) {
            int n = n0 + tx * 4 + j;
            float v = acc[i][j] + bias[n];
            if (RELU) v = fmaxf(v, 0.f);
            Out[(size_t)m * Nn + n] = v;
        }
    }
}

// ---------------------------------------------------------------------------
// launch
// ---------------------------------------------------------------------------
extern "C" void kernel_launch(void* const* d_in, const int* in_sizes, int n_in,
                              void* d_out, int out_size)
{
    const float* x     = (const float*)d_in[0];
    const void*  batch = d_in[1];
    const float* W1a   = (const float*)d_in[2];
    const float* b1a   = (const float*)d_in[3];
    const float* W2a   = (const float*)d_in[4];
    const float* b2a   = (const float*)d_in[5];
    const float* W1f   = (const float*)d_in[6];
    const float* b1f   = (const float*)d_in[7];
    const float* W2f   = (const float*)d_in[8];
    const float* b2f   = (const float*)d_in[9];
    float* out = (float*)d_out;

    const int N = in_sizes[0] / CC;  // nodes, derived from x (dtype-independent)
    const int G = out_size / CC;     // 4096

    float *comb_ptr = nullptr, *hid_ptr = nullptr;
    cudaGetSymbolAddress((void**)&comb_ptr, g_comb);
    cudaGetSymbolAddress((void**)&hid_ptr, g_hidden);

    cudaFuncSetAttribute(k1_attn, cudaFuncAttributeMaxDynamicSharedMemorySize, K1_SMEM);

    k0_init<<<1, 1>>>();
    k0_detect<<<(N + 255) / 256, 256>>>((const int*)batch, N);

    const int nblk = (N + 127) / 128;
    k1_attn<<<nblk, 256, K1_SMEM>>>(x, W1a, b1a, W2a, b2a, N);
    k2_pool<<<G, 256>>>(x, batch, N);
    k3_gemm<true ><<<dim3(CC / 64, G / 64), 256>>>(comb_ptr, W1f, b1f, hid_ptr, G, 3 * CC, CC);
    k3_gemm<false><<<dim3(CC / 64, G / 64), 256>>>(hid_ptr,  W2f, b2f, out,     G, CC,     CC);
}

// round 4
// speedup vs baseline: 1.7269x; 1.7269x over previous
#include <cuda_runtime.h>
#include <cuda_fp16.h>
#include <cstdint>
#include <math.h>

#define CC 256          // channels
#define GG_MAX 4096     // graphs
#define N_MAX 500000    // nodes

__device__ float g_aw[N_MAX + 256];
__device__ __align__(16) __half g_Wth[CC * CC];   // W1a^T in fp16: [n][k]
__device__ float g_comb[GG_MAX * 3 * CC];
__device__ float g_hidden[GG_MAX * CC];
__device__ int   g_is64;

// ---------------------------------------------------------------------------
// helpers
// ---------------------------------------------------------------------------
__device__ __forceinline__ uint32_t smem_u32(const void* p) {
    uint32_t a;
    asm("{ .reg .u64 t; cvta.to.shared.u64 t, %1; cvt.u32.u64 %0, t; }" : "=r"(a) : "l"(p));
    return a;
}

#define LDMX4(r0, r1, r2, r3, addr) \
    asm volatile("ldmatrix.sync.aligned.m8n8.x4.shared.b16 {%0,%1,%2,%3}, [%4];" \
        : "=r"(r0), "=r"(r1), "=r"(r2), "=r"(r3) : "r"(addr))

__device__ __forceinline__ void mma_f16(float* c, const uint32_t* a, uint32_t b0, uint32_t b1) {
    asm volatile(
        "mma.sync.aligned.m16n8k16.row.col.f32.f16.f16.f32 "
        "{%0,%1,%2,%3}, {%4,%5,%6,%7}, {%8,%9}, {%0,%1,%2,%3};"
        : "+f"(c[0]), "+f"(c[1]), "+f"(c[2]), "+f"(c[3])
        : "r"(a[0]), "r"(a[1]), "r"(a[2]), "r"(a[3]), "r"(b0), "r"(b1));
}

// ---------------------------------------------------------------------------
// batch dtype detection (int32 vs int64 view; sorted-ness discriminates)
// ---------------------------------------------------------------------------
__global__ void k0_init() { g_is64 = 0; }
__global__ void k0_detect(const int* __restrict__ b32, int N) {
    int i = blockIdx.x * blockDim.x + threadIdx.x;
    if (i < N - 1) {
        int a = b32[i], b = b32[i + 1];
        if (a > b || a < 0 || b < 0) g_is64 = 1;
    }
}
__device__ __forceinline__ long long bval(const void* b, int i) {
    if (g_is64) return ((const long long*)b)[i];
    return (long long)((const int*)b)[i];
}

// ---------------------------------------------------------------------------
// W1a -> transposed fp16: g_Wth[n][k] = half(W1a[k][n])
// ---------------------------------------------------------------------------
__global__ void k_wt(const float* __restrict__ W1a) {
    int n = blockIdx.x, k = threadIdx.x;
    g_Wth[n * CC + k] = __float2half(W1a[k * CC + n]);
}

// ---------------------------------------------------------------------------
// K1: fused attention MLP with fp16 mma.sync (m16n8k16), persistent CTAs.
//   aw[n] = sigmoid(relu(x@W1a + b1a) @ W2a + b2a)
// B (= W1a^T, 256x256 fp16, 128KB) stays in smem for the whole kernel.
// Per tile: 128 nodes. A tile 128x256 fp16 (64KB), SW-swizzled.
// 8 warps = 4 m-groups (32 rows) x 2 n-halves (128 cols).
// Epilogue: relu -> dot W2a -> cross-warp smem reduce -> sigmoid.
// smem row stride = 512B, 16B-chunk swizzle: chunk ^= (row & 7).
// ---------------------------------------------------------------------------
#define A_OFF   0
#define B_OFF   65536
#define SB1_OFF 196608
#define SW2_OFF 197632
#define K1_SMEM 198656

__global__ void __launch_bounds__(256, 1) k1_fp16(
    const float* __restrict__ x, const float* __restrict__ b1a,
    const float* __restrict__ W2a, const float* __restrict__ b2a,
    int N, int nTiles)
{
    extern __shared__ char sm[];
    const uint32_t sb = smem_u32(sm);
    float* sB1 = (float*)(sm + SB1_OFF);
    float* sW2 = (float*)(sm + SW2_OFF);
    __shared__ float pbuf[2][4][32];

    const int tid  = threadIdx.x;
    const int lane = tid & 31;
    const int w    = tid >> 5;
    const int mw   = w & 3;       // m-group: rows mw*32 .. mw*32+31
    const int ns   = w >> 2;      // n-half: cols ns*128 .. +127

    sB1[tid] = b1a[tid];
    sW2[tid] = W2a[tid];
    const float b2 = b2a[0];

    // Fill B once: g_Wth [256n][256k] fp16 -> swizzled smem (512B rows)
    #pragma unroll 4
    for (int it = 0; it < 32; ++it) {
        int idx = tid + it * 256;          // 8192 16B-chunks
        int row = idx >> 5, c = idx & 31;
        uint4 v = *(const uint4*)(g_Wth + (size_t)row * CC + c * 8);
        *(uint4*)(sm + B_OFF + row * 512 + ((c ^ (row & 7)) << 4)) = v;
    }

    const int lrow   = lane & 15;
    const int lchunk = lane >> 4;
    const int qr = lane >> 2, qc = lane & 3;
    const int mrow0 = mw * 32;

    for (int tile = blockIdx.x; tile < nTiles; tile += gridDim.x) {
        const int m0 = tile * 128;
        __syncthreads();   // previous tile's ldmatrix/pbuf use complete

        // Fill A: x rows m0..m0+127, fp32 -> fp16, swizzled
        #pragma unroll 4
        for (int it = 0; it < 16; ++it) {
            int idx = tid + it * 256;      // 4096 16B-chunks
            int row = idx >> 5, c = idx & 31;
            int node = m0 + row;
            float4 v0 = make_float4(0.f, 0.f, 0.f, 0.f);
            float4 v1 = v0;
            if (node < N) {
                const float4* xr = (const float4*)(x + (size_t)node * CC);
                v0 = xr[c * 2]; v1 = xr[c * 2 + 1];
            }
            __half2 h0 = __floats2half2_rn(v0.x, v0.y), h1 = __floats2half2_rn(v0.z, v0.w);
            __half2 h2 = __floats2half2_rn(v1.x, v1.y), h3 = __floats2half2_rn(v1.z, v1.w);
            uint4 u;
            u.x = *(uint32_t*)&h0; u.y = *(uint32_t*)&h1;
            u.z = *(uint32_t*)&h2; u.w = *(uint32_t*)&h3;
            *(uint4*)(sm + A_OFF + row * 512 + ((c ^ (row & 7)) << 4)) = u;
        }
        __syncthreads();

        float p[4] = {0.f, 0.f, 0.f, 0.f};   // rows mrow0 + {qr, qr+8, 16+qr, 24+qr}

        #pragma unroll 1
        for (int nq = 0; nq < 2; ++nq) {
            const int ncol0 = ns * 128 + nq * 64;
            float acc[2][8][4];
            #pragma unroll
            for (int mt = 0; mt < 2; ++mt)
                #pragma unroll
                for (int nt = 0; nt < 8; ++nt) {
                    acc[mt][nt][0] = 0.f; acc[mt][nt][1] = 0.f;
                    acc[mt][nt][2] = 0.f; acc[mt][nt][3] = 0.f;
                }

            #pragma unroll 2
            for (int ks = 0; ks < 16; ++ks) {
                const int kc = ks * 2 + lchunk;
                uint32_t a[2][4];
                #pragma unroll
                for (int mt = 0; mt < 2; ++mt) {
                    int row = mrow0 + mt * 16 + lrow;
                    uint32_t ad = sb + A_OFF + row * 512 + ((kc ^ (row & 7)) << 4);
                    LDMX4(a[mt][0], a[mt][1], a[mt][2], a[mt][3], ad);
                }
                uint32_t b[4][4];
                #pragma unroll
                for (int bq = 0; bq < 4; ++bq) {
                    int nr = ncol0 + bq * 16 + lrow;
                    uint32_t ad = sb + B_OFF + nr * 512 + ((kc ^ (nr & 7)) << 4);
                    LDMX4(b[bq][0], b[bq][1], b[bq][2], b[bq][3], ad);
                }
                #pragma unroll
                for (int mt = 0; mt < 2; ++mt)
                    #pragma unroll
                    for (int bq = 0; bq < 4; ++bq) {
                        mma_f16(acc[mt][2 * bq],     a[mt], b[bq][0], b[bq][2]);
                        mma_f16(acc[mt][2 * bq + 1], a[mt], b[bq][1], b[bq][3]);
                    }
            }

            // epilogue: relu + dot with W2a
            #pragma unroll
            for (int mt = 0; mt < 2; ++mt)
                #pragma unroll
                for (int nt = 0; nt < 8; ++nt) {
                    int col = ncol0 + nt * 8 + qc * 2;
                    float bA = sB1[col], bB = sB1[col + 1];
                    float wA = sW2[col], wB = sW2[col + 1];
                    p[mt * 2 + 0] += fmaxf(acc[mt][nt][0] + bA, 0.f) * wA
                                   + fmaxf(acc[mt][nt][1] + bB, 0.f) * wB;
                    p[mt * 2 + 1] += fmaxf(acc[mt][nt][2] + bA, 0.f) * wA
                                   + fmaxf(acc[mt][nt][3] + bB, 0.f) * wB;
                }
        }

        // reduce over the 4 lanes of each quad (cols within quad)
        #pragma unroll
        for (int j = 0; j < 4; ++j) {
            p[j] += __shfl_xor_sync(0xffffffffu, p[j], 1);
            p[j] += __shfl_xor_sync(0xffffffffu, p[j], 2);
        }
        if (qc == 0) {
            pbuf[ns][mw][qr]      = p[0];
            pbuf[ns][mw][qr + 8]  = p[1];
            pbuf[ns][mw][qr + 16] = p[2];
            pbuf[ns][mw][qr + 24] = p[3];
        }
        __syncthreads();
        if (tid < 128) {
            int mw2 = tid >> 5, r32 = tid & 31;
            float s = pbuf[0][mw2][r32] + pbuf[1][mw2][r32];
            int node = m0 + mw2 * 32 + r32;
            if (node < N) g_aw[node] = 1.f / (1.f + expf(-(s + b2)));
        }
    }
}

// ---------------------------------------------------------------------------
// K2: segment pooling. 256 threads = 64 float4-channel groups x 4 row lanes.
// batch sorted -> contiguous segments, binary-search bounds, no atomics.
// ---------------------------------------------------------------------------
__global__ void __launch_bounds__(256) k2_pool(
    const float* __restrict__ x, const void* __restrict__ batch, int N)
{
    const int g = blockIdx.x;
    __shared__ int sR[2];
    __shared__ float4 red[3][4][64];
    const int tid = threadIdx.x;
    const int cq  = tid & 63;
    const int r   = tid >> 6;

    if (tid == 0) {
        int lo = 0, hi = N;
        while (lo < hi) { int mid = (lo + hi) >> 1; if (bval(batch, mid) < (long long)g) lo = mid + 1; else hi = mid; }
        sR[0] = lo;
        hi = N;
        while (lo < hi) { int mid = (lo + hi) >> 1; if (bval(batch, mid) < (long long)g + 1) lo = mid + 1; else hi = mid; }
        sR[1] = lo;
    }
    __syncthreads();
    const int s = sR[0], e = sR[1];

    float4 sum = make_float4(0.f, 0.f, 0.f, 0.f);
    float4 att = make_float4(0.f, 0.f, 0.f, 0.f);
    float4 mx  = make_float4(-INFINITY, -INFINITY, -INFINITY, -INFINITY);

    for (int i = s + r; i < e; i += 4) {
        float4 v = ((const float4*)(x + (size_t)i * CC))[cq];
        float wt = g_aw[i];
        sum.x += v.x; sum.y += v.y; sum.z += v.z; sum.w += v.w;
        att.x = fmaf(v.x, wt, att.x); att.y = fmaf(v.y, wt, att.y);
        att.z = fmaf(v.z, wt, att.z); att.w = fmaf(v.w, wt, att.w);
        mx.x = fmaxf(mx.x, v.x); mx.y = fmaxf(mx.y, v.y);
        mx.z = fmaxf(mx.z, v.z); mx.w = fmaxf(mx.w, v.w);
    }
    red[0][r][cq] = sum; red[1][r][cq] = att; red[2][r][cq] = mx;
    __syncthreads();

    if (r == 0) {
        #pragma unroll
        for (int k = 1; k < 4; ++k) {
            float4 a = red[0][k][cq], b = red[1][k][cq], m = red[2][k][cq];
            sum.x += a.x; sum.y += a.y; sum.z += a.z; sum.w += a.w;
            att.x += b.x; att.y += b.y; att.z += b.z; att.w += b.w;
            mx.x = fmaxf(mx.x, m.x); mx.y = fmaxf(mx.y, m.y);
            mx.z = fmaxf(mx.z, m.z); mx.w = fmaxf(mx.w, m.w);
        }
        float inv = 1.f / fmaxf((float)(e - s), 1.f);
        float4 mean = make_float4(sum.x * inv, sum.y * inv, sum.z * inv, sum.w * inv);
        float4 mxo = (e > s) ? mx : make_float4(0.f, 0.f, 0.f, 0.f);
        float* comb = g_comb + (size_t)g * (3 * CC);
        ((float4*)(comb))[cq]          = att;
        ((float4*)(comb + CC))[cq]     = mean;
        ((float4*)(comb + 2 * CC))[cq] = mxo;
    }
}

// ---------------------------------------------------------------------------
// K3: fp32 tiled GEMM with bias (+optional relu). 64x64 tile, 256 threads.
// ---------------------------------------------------------------------------
template <bool RELU>
__global__ void __launch_bounds__(256) k3_gemm(
    const float* __restrict__ A, const float* __restrict__ B,
    const float* __restrict__ bias, float* __restrict__ Out,
    int M, int K, int Nn)
{
    __shared__ float sA[16][68];
    __shared__ float sB[16][68];
    const int t  = threadIdx.x;
    const int tx = t & 15, ty = t >> 4;
    const int m0 = blockIdx.y * 64, n0 = blockIdx.x * 64;
    float acc[4][4] = {};

    for (int kt = 0; kt < K; kt += 16) {
        #pragma unroll
        for (int i = 0; i < 4; ++i) {
            int idx = t + i * 256;
            int m = idx >> 4, k = idx & 15;
            sA[k][m] = A[(size_t)(m0 + m) * K + kt + k];
        }
        #pragma unroll
        for (int i = 0; i < 4; ++i) {
            int idx = t + i * 256;
            int k = idx >> 6, n = idx & 63;
            sB[k][n] = B[(size_t)(kt + k) * Nn + n0 + n];
        }
        __syncthreads();
        #pragma unroll
        for (int kk = 0; kk < 16; ++kk) {
            float4 a4 = *(const float4*)&sA[kk][ty * 4];
            float4 b4 = *(const float4*)&sB[kk][tx * 4];
            float av[4] = {a4.x, a4.y, a4.z, a4.w};
            float bv[4] = {b4.x, b4.y, b4.z, b4.w};
            #pragma unroll
            for (int i = 0; i < 4; ++i)
                #pragma unroll
                for (int j = 0; j < 4; ++j)
                    acc[i][j] = fmaf(av[i], bv[j], acc[i][j]);
        }
        __syncthreads();
    }

    #pragma unroll
    for (int i = 0; i < 4; ++i) {
        int m = m0 + ty * 4 + i;
        #pragma unroll
        for (int j = 0; j < 4; ++j) {
            int n = n0 + tx * 4 + j;
            float v = acc[i][j] + bias[n];
            if (RELU) v = fmaxf(v, 0.f);
            Out[(size_t)m * Nn + n] = v;
        }
    }
}

// ---------------------------------------------------------------------------
// launch
// ---------------------------------------------------------------------------
extern "C" void kernel_launch(void* const* d_in, const int* in_sizes, int n_in,
                              void* d_out, int out_size)
{
    const float* x     = (const float*)d_in[0];
    const void*  batch = d_in[1];
    const float* W1a   = (const float*)d_in[2];
    const float* b1a   = (const float*)d_in[3];
    const float* W2a   = (const float*)d_in[4];
    const float* b2a   = (const float*)d_in[5];
    const float* W1f   = (const float*)d_in[6];
    const float* b1f   = (const float*)d_in[7];
    const float* W2f   = (const float*)d_in[8];
    const float* b2f   = (const float*)d_in[9];
    float* out = (float*)d_out;

    const int N = in_sizes[0] / CC;
    const int G = out_size / CC;

    float *comb_ptr = nullptr, *hid_ptr = nullptr;
    cudaGetSymbolAddress((void**)&comb_ptr, g_comb);
    cudaGetSymbolAddress((void**)&hid_ptr, g_hidden);

    cudaFuncSetAttribute(k1_fp16, cudaFuncAttributeMaxDynamicSharedMemorySize, K1_SMEM);

    k0_init<<<1, 1>>>();
    k0_detect<<<(N + 255) / 256, 256>>>((const int*)batch, N);
    k_wt<<<CC, CC>>>(W1a);

    const int nTiles = (N + 127) / 128;
    const int grid = nTiles < 148 ? nTiles : 148;
    k1_fp16<<<grid, 256, K1_SMEM>>>(x, b1a, W2a, b2a, N, nTiles);
    k2_pool<<<G, 256>>>(x, batch, N);
    k3_gemm<true ><<<dim3(CC / 64, G / 64), 256>>>(comb_ptr, W1f, b1f, hid_ptr, G, 3 * CC, CC);
    k3_gemm<false><<<dim3(CC / 64, G / 64), 256>>>(hid_ptr,  W2f, b2f, out,     G, CC,     CC);
}

// round 5
// speedup vs baseline: 1.7710x; 1.0255x over previous
#include <cuda_runtime.h>
#include <cuda_fp16.h>
#include <cstdint>
#include <math.h>

#define CC 256          // channels
#define GG_MAX 4096     // graphs
#define N_MAX 500000    // nodes

__device__ float g_aw[N_MAX + 256];
__device__ __align__(16) __half g_Wth[CC * CC];   // W1a^T in fp16: [n][k]
__device__ float g_comb[GG_MAX * 3 * CC];
__device__ float g_hidden[GG_MAX * CC];
__device__ int   g_is64;

// ---------------------------------------------------------------------------
// helpers
// ---------------------------------------------------------------------------
__device__ __forceinline__ uint32_t smem_u32(const void* p) {
    uint32_t a;
    asm("{ .reg .u64 t; cvta.to.shared.u64 t, %1; cvt.u32.u64 %0, t; }" : "=r"(a) : "l"(p));
    return a;
}

#define LDMX4(r0, r1, r2, r3, addr) \
    asm volatile("ldmatrix.sync.aligned.m8n8.x4.shared.b16 {%0,%1,%2,%3}, [%4];" \
        : "=r"(r0), "=r"(r1), "=r"(r2), "=r"(r3) : "r"(addr))

__device__ __forceinline__ void mma_f16(float* c, const uint32_t* a, uint32_t b0, uint32_t b1) {
    asm volatile(
        "mma.sync.aligned.m16n8k16.row.col.f32.f16.f16.f32 "
        "{%0,%1,%2,%3}, {%4,%5,%6,%7}, {%8,%9}, {%0,%1,%2,%3};"
        : "+f"(c[0]), "+f"(c[1]), "+f"(c[2]), "+f"(c[3])
        : "r"(a[0]), "r"(a[1]), "r"(a[2]), "r"(a[3]), "r"(b0), "r"(b1));
}

#define CP_COMMIT() asm volatile("cp.async.commit_group;" ::: "memory")
#define CP_WAIT0()  asm volatile("cp.async.wait_group 0;" ::: "memory")

// ---------------------------------------------------------------------------
// batch dtype detection (int32 vs int64 view; sorted-ness discriminates)
// ---------------------------------------------------------------------------
__global__ void k0_init() { g_is64 = 0; }
__global__ void k0_detect(const int* __restrict__ b32, int N) {
    int i = blockIdx.x * blockDim.x + threadIdx.x;
    if (i < N - 1) {
        int a = b32[i], b = b32[i + 1];
        if (a > b || a < 0 || b < 0) g_is64 = 1;
    }
}
__device__ __forceinline__ long long bval(const void* b, int i) {
    if (g_is64) return ((const long long*)b)[i];
    return (long long)((const int*)b)[i];
}

// ---------------------------------------------------------------------------
// W1a -> transposed fp16: g_Wth[n][k] = half(W1a[k][n])
// ---------------------------------------------------------------------------
__global__ void k_wt(const float* __restrict__ W1a) {
    int n = blockIdx.x, k = threadIdx.x;
    g_Wth[n * CC + k] = __float2half(W1a[k * CC + n]);
}

// ---------------------------------------------------------------------------
// K1: fused attention MLP, fp16 mma.sync, persistent CTAs, pipelined.
//   aw[n] = sigmoid(relu(x@W1a + b1a) @ W2a + b2a)
// B (W1a^T, 256x256 fp16, 128KB) resident in smem for the whole kernel.
// Per tile: 32 nodes. A staged fp32 via cp.async (double-buffered, 32KB/stage),
// converted to a swizzled fp16 tile (16KB), prefetch of tile t+1 issued before
// the mma of tile t (overlaps DRAM with tensor work).
// 8 warps = 2 m-groups (16 rows) x 4 n-groups (64 cols).
// ---------------------------------------------------------------------------
#define TILE_M   32
#define A32_OFF  0          // 2 x 32768
#define A16_OFF  65536      // 16384
#define BSM_OFF  81920      // 131072
#define SB1_OFF  212992
#define SW2_OFF  214016
#define PBUF_OFF 215040     // 128 floats
#define K1_SMEM  215552

__device__ __forceinline__ void k1_load_stage(uint32_t sb, char* sm,
                                              const float* __restrict__ x,
                                              int m0, int N, int s) {
    const int tid = threadIdx.x;
    #pragma unroll
    for (int u = 0; u < 8; ++u) {
        int idx = tid + u * 256;            // 2048 16B-chunks: 32 rows x 64 f4
        int row = idx >> 6, c4 = idx & 63;
        int node = m0 + row;
        const float* src = x + (size_t)(node < N ? node : 0) * CC + c4 * 4;
        uint32_t dst = sb + A32_OFF + s * 32768 + row * 1024 + c4 * 16;
        uint32_t sz = (node < N) ? 16u : 0u;
        asm volatile("cp.async.cg.shared.global [%0], [%1], 16, %2;"
                     :: "r"(dst), "l"(src), "r"(sz));
    }
    CP_COMMIT();
}

__global__ void __launch_bounds__(256, 1) k1_fp16(
    const float* __restrict__ x, const float* __restrict__ b1a,
    const float* __restrict__ W2a, const float* __restrict__ b2a,
    int N, int nTiles)
{
    extern __shared__ char sm[];
    const uint32_t sb = smem_u32(sm);
    float* sB1  = (float*)(sm + SB1_OFF);
    float* sW2  = (float*)(sm + SW2_OFF);
    float* pbuf = (float*)(sm + PBUF_OFF);

    const int tid  = threadIdx.x;
    const int lane = tid & 31;
    const int w    = tid >> 5;
    const int mw   = w & 1;       // m-group: rows mw*16 .. +15
    const int ns   = w >> 1;      // n-group: cols ns*64 .. +63

    sB1[tid] = b1a[tid];
    sW2[tid] = W2a[tid];
    const float b2 = b2a[0];

    // Fill B once: g_Wth [256n][256k] fp16 -> swizzled smem (512B rows)
    #pragma unroll 4
    for (int it = 0; it < 32; ++it) {
        int idx = tid + it * 256;          // 8192 16B-chunks
        int row = idx >> 5, c = idx & 31;
        uint4 v = *(const uint4*)(g_Wth + (size_t)row * CC + c * 8);
        *(uint4*)(sm + BSM_OFF + row * 512 + ((c ^ (row & 7)) << 4)) = v;
    }

    const int lrow   = lane & 15;
    const int lchunk = lane >> 4;
    const int qr = lane >> 2, qc = lane & 3;
    const int mrow0 = mw * 16;
    const int ncol0 = ns * 64;

    // preload first tile into stage 0
    if (blockIdx.x < nTiles)
        k1_load_stage(sb, sm, x, blockIdx.x * TILE_M, N, 0);

    int i = 0;
    for (int t = blockIdx.x; t < nTiles; t += gridDim.x, ++i) {
        const int s  = i & 1;
        const int m0 = t * TILE_M;

        CP_WAIT0();
        __syncthreads();          // staged tile t visible to all; pbuf free

        // convert A32[s] -> A16 (swizzled fp16)
        #pragma unroll
        for (int it = 0; it < 4; ++it) {
            int idx = tid + it * 256;      // 1024 16B fp16 chunks: 32 rows x 32
            int row = idx >> 5, c = idx & 31;
            const float4* src = (const float4*)(sm + A32_OFF + s * 32768 + row * 1024 + c * 32);
            float4 v0 = src[0], v1 = src[1];
            __half2 h0 = __floats2half2_rn(v0.x, v0.y), h1 = __floats2half2_rn(v0.z, v0.w);
            __half2 h2 = __floats2half2_rn(v1.x, v1.y), h3 = __floats2half2_rn(v1.z, v1.w);
            uint4 u;
            u.x = *(uint32_t*)&h0; u.y = *(uint32_t*)&h1;
            u.z = *(uint32_t*)&h2; u.w = *(uint32_t*)&h3;
            *(uint4*)(sm + A16_OFF + row * 512 + ((c ^ (row & 7)) << 4)) = u;
        }
        __syncthreads();          // A16 ready; A32[s] free for reuse

        // prefetch tile t+gridDim into the other stage (overlaps mma below)
        int tn = t + gridDim.x;
        if (tn < nTiles)
            k1_load_stage(sb, sm, x, tn * TILE_M, N, s ^ 1);

        // mma: m16 x n64 x k256 per warp
        float acc[8][4];
        #pragma unroll
        for (int nt = 0; nt < 8; ++nt) {
            acc[nt][0] = 0.f; acc[nt][1] = 0.f; acc[nt][2] = 0.f; acc[nt][3] = 0.f;
        }
        #pragma unroll 4
        for (int ks = 0; ks < 16; ++ks) {
            const int kc = ks * 2 + lchunk;
            uint32_t a[4];
            {
                int row = mrow0 + lrow;
                uint32_t ad = sb + A16_OFF + row * 512 + ((kc ^ (row & 7)) << 4);
                LDMX4(a[0], a[1], a[2], a[3], ad);
            }
            uint32_t b[4][4];
            #pragma unroll
            for (int bq = 0; bq < 4; ++bq) {
                int nr = ncol0 + bq * 16 + lrow;
                uint32_t ad = sb + BSM_OFF + nr * 512 + ((kc ^ (nr & 7)) << 4);
                LDMX4(b[bq][0], b[bq][1], b[bq][2], b[bq][3], ad);
            }
            #pragma unroll
            for (int bq = 0; bq < 4; ++bq) {
                mma_f16(acc[2 * bq],     a, b[bq][0], b[bq][2]);
                mma_f16(acc[2 * bq + 1], a, b[bq][1], b[bq][3]);
            }
        }

        // epilogue: relu -> dot W2a
        float p0 = 0.f, p1 = 0.f;
        #pragma unroll
        for (int nt = 0; nt < 8; ++nt) {
            int col = ncol0 + nt * 8 + qc * 2;
            float bA = sB1[col], bB = sB1[col + 1];
            float wA = sW2[col], wB = sW2[col + 1];
            p0 += fmaxf(acc[nt][0] + bA, 0.f) * wA + fmaxf(acc[nt][1] + bB, 0.f) * wB;
            p1 += fmaxf(acc[nt][2] + bA, 0.f) * wA + fmaxf(acc[nt][3] + bB, 0.f) * wB;
        }
        p0 += __shfl_xor_sync(0xffffffffu, p0, 1);
        p0 += __shfl_xor_sync(0xffffffffu, p0, 2);
        p1 += __shfl_xor_sync(0xffffffffu, p1, 1);
        p1 += __shfl_xor_sync(0xffffffffu, p1, 2);
        if (qc == 0) {
            pbuf[ns * 32 + mrow0 + qr]     = p0;
            pbuf[ns * 32 + mrow0 + qr + 8] = p1;
        }
        __syncthreads();
        if (tid < 32) {
            float ssum = pbuf[tid] + pbuf[32 + tid] + pbuf[64 + tid] + pbuf[96 + tid];
            int node = m0 + tid;
            if (node < N) g_aw[node] = 1.f / (1.f + expf(-(ssum + b2)));
        }
    }
}

// ---------------------------------------------------------------------------
// K2: segment pooling. 256 threads = 64 float4-channel groups x 4 row lanes.
// ---------------------------------------------------------------------------
__global__ void __launch_bounds__(256) k2_pool(
    const float* __restrict__ x, const void* __restrict__ batch, int N)
{
    const int g = blockIdx.x;
    __shared__ int sR[2];
    __shared__ float4 red[3][4][64];
    const int tid = threadIdx.x;
    const int cq  = tid & 63;
    const int r   = tid >> 6;

    if (tid == 0) {
        int lo = 0, hi = N;
        while (lo < hi) { int mid = (lo + hi) >> 1; if (bval(batch, mid) < (long long)g) lo = mid + 1; else hi = mid; }
        sR[0] = lo;
        hi = N;
        while (lo < hi) { int mid = (lo + hi) >> 1; if (bval(batch, mid) < (long long)g + 1) lo = mid + 1; else hi = mid; }
        sR[1] = lo;
    }
    __syncthreads();
    const int s = sR[0], e = sR[1];

    float4 sum = make_float4(0.f, 0.f, 0.f, 0.f);
    float4 att = make_float4(0.f, 0.f, 0.f, 0.f);
    float4 mx  = make_float4(-INFINITY, -INFINITY, -INFINITY, -INFINITY);

    for (int i = s + r; i < e; i += 4) {
        float4 v = ((const float4*)(x + (size_t)i * CC))[cq];
        float wt = g_aw[i];
        sum.x += v.x; sum.y += v.y; sum.z += v.z; sum.w += v.w;
        att.x = fmaf(v.x, wt, att.x); att.y = fmaf(v.y, wt, att.y);
        att.z = fmaf(v.z, wt, att.z); att.w = fmaf(v.w, wt, att.w);
        mx.x = fmaxf(mx.x, v.x); mx.y = fmaxf(mx.y, v.y);
        mx.z = fmaxf(mx.z, v.z); mx.w = fmaxf(mx.w, v.w);
    }
    red[0][r][cq] = sum; red[1][r][cq] = att; red[2][r][cq] = mx;
    __syncthreads();

    if (r == 0) {
        #pragma unroll
        for (int k = 1; k < 4; ++k) {
            float4 a = red[0][k][cq], b = red[1][k][cq], m = red[2][k][cq];
            sum.x += a.x; sum.y += a.y; sum.z += a.z; sum.w += a.w;
            att.x += b.x; att.y += b.y; att.z += b.z; att.w += b.w;
            mx.x = fmaxf(mx.x, m.x); mx.y = fmaxf(mx.y, m.y);
            mx.z = fmaxf(mx.z, m.z); mx.w = fmaxf(mx.w, m.w);
        }
        float inv = 1.f / fmaxf((float)(e - s), 1.f);
        float4 mean = make_float4(sum.x * inv, sum.y * inv, sum.z * inv, sum.w * inv);
        float4 mxo = (e > s) ? mx : make_float4(0.f, 0.f, 0.f, 0.f);
        float* comb = g_comb + (size_t)g * (3 * CC);
        ((float4*)(comb))[cq]          = att;
        ((float4*)(comb + CC))[cq]     = mean;
        ((float4*)(comb + 2 * CC))[cq] = mxo;
    }
}

// ---------------------------------------------------------------------------
// K3: fp32 tiled GEMM with bias (+optional relu). 64x64 tile, 256 threads.
// ---------------------------------------------------------------------------
template <bool RELU>
__global__ void __launch_bounds__(256) k3_gemm(
    const float* __restrict__ A, const float* __restrict__ B,
    const float* __restrict__ bias, float* __restrict__ Out,
    int M, int K, int Nn)
{
    __shared__ float sA[16][68];
    __shared__ float sB[16][68];
    const int t  = threadIdx.x;
    const int tx = t & 15, ty = t >> 4;
    const int m0 = blockIdx.y * 64, n0 = blockIdx.x * 64;
    float acc[4][4] = {};

    for (int kt = 0; kt < K; kt += 16) {
        #pragma unroll
        for (int i = 0; i < 4; ++i) {
            int idx = t + i * 256;
            int m = idx >> 4, k = idx & 15;
            sA[k][m] = A[(size_t)(m0 + m) * K + kt + k];
        }
        #pragma unroll
        for (int i = 0; i < 4; ++i) {
            int idx = t + i * 256;
            int k = idx >> 6, n = idx & 63;
            sB[k][n] = B[(size_t)(kt + k) * Nn + n0 + n];
        }
        __syncthreads();
        #pragma unroll
        for (int kk = 0; kk < 16; ++kk) {
            float4 a4 = *(const float4*)&sA[kk][ty * 4];
            float4 b4 = *(const float4*)&sB[kk][tx * 4];
            float av[4] = {a4.x, a4.y, a4.z, a4.w};
            float bv[4] = {b4.x, b4.y, b4.z, b4.w};
            #pragma unroll
            for (int i = 0; i < 4; ++i)
                #pragma unroll
                for (int j = 0; j < 4; ++j)
                    acc[i][j] = fmaf(av[i], bv[j], acc[i][j]);
        }
        __syncthreads();
    }

    #pragma unroll
    for (int i = 0; i < 4; ++i) {
        int m = m0 + ty * 4 + i;
        #pragma unroll
        for (int j = 0; j < 4; ++j) {
            int n = n0 + tx * 4 + j;
            float v = acc[i][j] + bias[n];
            if (RELU) v = fmaxf(v, 0.f);
            Out[(size_t)m * Nn + n] = v;
        }
    }
}

// ---------------------------------------------------------------------------
// launch
// ---------------------------------------------------------------------------
extern "C" void kernel_launch(void* const* d_in, const int* in_sizes, int n_in,
                              void* d_out, int out_size)
{
    const float* x     = (const float*)d_in[0];
    const void*  batch = d_in[1];
    const float* W1a   = (const float*)d_in[2];
    const float* b1a   = (const float*)d_in[3];
    const float* W2a   = (const float*)d_in[4];
    const float* b2a   = (const float*)d_in[5];
    const float* W1f   = (const float*)d_in[6];
    const float* b1f   = (const float*)d_in[7];
    const float* W2f   = (const float*)d_in[8];
    const float* b2f   = (const float*)d_in[9];
    float* out = (float*)d_out;

    const int N = in_sizes[0] / CC;
    const int G = out_size / CC;

    float *comb_ptr = nullptr, *hid_ptr = nullptr;
    cudaGetSymbolAddress((void**)&comb_ptr, g_comb);
    cudaGetSymbolAddress((void**)&hid_ptr, g_hidden);

    cudaFuncSetAttribute(k1_fp16, cudaFuncAttributeMaxDynamicSharedMemorySize, K1_SMEM);

    k0_init<<<1, 1>>>();
    k0_detect<<<(N + 255) / 256, 256>>>((const int*)batch, N);
    k_wt<<<CC, CC>>>(W1a);

    const int nTiles = (N + TILE_M - 1) / TILE_M;
    const int grid = nTiles < 148 ? nTiles : 148;
    k1_fp16<<<grid, 256, K1_SMEM>>>(x, b1a, W2a, b2a, N, nTiles);
    k2_pool<<<G, 256>>>(x, batch, N);
    k3_gemm<true ><<<dim3(CC / 64, G / 64), 256>>>(comb_ptr, W1f, b1f, hid_ptr, G, 3 * CC, CC);
    k3_gemm<false><<<dim3(CC / 64, G / 64), 256>>>(hid_ptr,  W2f, b2f, out,     G, CC,     CC);
}